// round 14
// baseline (speedup 1.0000x reference)
#include <cuda_runtime.h>
#include <cuda_bf16.h>
#include <math.h>

#define BB 2
#define SS 2048
#define EE 768
#define HH 12
#define DK 64

// Packed bf16x2 hi/lo interchange buffers (allocation-free)
__device__ unsigned g_Qh[BB*HH*SS*32], g_Ql[BB*HH*SS*32];  // [bhs][dk2], pre-scaled 1/8
__device__ unsigned g_Kh[BB*HH*SS*32], g_Kl[BB*HH*SS*32];  // [bhs][dk2]
__device__ unsigned g_Vh[BB*HH*SS*32], g_Vl[BB*HH*SS*32];  // [bhs][dk2]
__device__ unsigned g_Ch[BB*SS*384],  g_Cl[BB*SS*384];     // concat [m][e2]

__device__ __forceinline__ void split2(float x0, float x1, unsigned& hi, unsigned& lo) {
    __nv_bfloat162 h2 = __floats2bfloat162_rn(x0, x1);
    float h0 = __bfloat162float(__low2bfloat16(h2));
    float h1 = __bfloat162float(__high2bfloat16(h2));
    __nv_bfloat162 l2 = __floats2bfloat162_rn(x0 - h0, x1 - h1);
    hi = *reinterpret_cast<unsigned*>(&h2);
    lo = *reinterpret_cast<unsigned*>(&l2);
}

__device__ __forceinline__ void mma16(float c[4], const unsigned a[4], const unsigned* b) {
    asm volatile(
        "mma.sync.aligned.m16n8k16.row.col.f32.bf16.bf16.f32 "
        "{%0,%1,%2,%3},{%4,%5,%6,%7},{%8,%9},{%0,%1,%2,%3};"
        : "+f"(c[0]), "+f"(c[1]), "+f"(c[2]), "+f"(c[3])
        : "r"(a[0]), "r"(a[1]), "r"(a[2]), "r"(a[3]), "r"(b[0]), "r"(b[1]));
}

__device__ __forceinline__ void ldsm_x4(unsigned r[4], const void* p) {
    unsigned addr = (unsigned)__cvta_generic_to_shared(p);
    asm volatile("ldmatrix.sync.aligned.m8n8.x4.shared.b16 {%0,%1,%2,%3}, [%4];"
                 : "=r"(r[0]), "=r"(r[1]), "=r"(r[2]), "=r"(r[3]) : "r"(addr));
}

__device__ __forceinline__ void ldsm_x4_trans(unsigned r[4], const void* p) {
    unsigned addr = (unsigned)__cvta_generic_to_shared(p);
    asm volatile("ldmatrix.sync.aligned.m8n8.x4.trans.shared.b16 {%0,%1,%2,%3}, [%4];"
                 : "=r"(r[0]), "=r"(r[1]), "=r"(r[2]), "=r"(r[3]) : "r"(addr));
}

#define GW 20
#define GEMM_STAGE (4*128*GW)          // words per stage: Ah|Al|Bh|Bl
#define GEMM_SMEM  (2*GEMM_STAGE*4)    // bytes

// ---------------------------------------------------------------------------
// Fused QKV GEMM: 128x128 tiles, 256 threads, 2-stage smem pipeline,
// one sync per k-block. grid=(32,18). Epilogue -> packed hi/lo Q(x1/8)/K/V.
// ---------------------------------------------------------------------------
__global__ __launch_bounds__(256) void qkv_gemm_kernel(
    const float* __restrict__ Xq, const float* __restrict__ Xk, const float* __restrict__ Xv,
    const float* __restrict__ Wq, const float* __restrict__ Wk, const float* __restrict__ Wv)
{
    extern __shared__ unsigned dsm[];

    int bx = blockIdx.x, by = blockIdx.y;
    int t = threadIdx.x, w = t >> 5, l = t & 31;
    int t4 = l & 3;
    int g = l >> 2;
    int lj = l >> 3, lr = l & 7;
    int m0 = bx * 128;
    int n0 = by * 128;

    int which = n0 / EE;
    int rem = n0 - which * EE;
    const float* A  = (which == 0) ? Xq : (which == 1) ? Xk : Xv;
    const float* Ws = (which == 0) ? Wq : (which == 1) ? Wk : Wv;
    const float* Bbase = Ws + (size_t)(rem / 64) * EE * DK;

    float acc[16][4] = {};
    int r0 = 16*w + g;

    int arow = 16*w + lr + (lj & 1) * 8;
    int acol_q = (lj >> 1) * 4;
    int brow_off = lr + (lj >> 1) * 8;
    int bcol_q = (lj & 1) * 4;

    int ar = t >> 4, ak2 = t & 15;
    int bn = t & 127, bk2 = t >> 7;
    int hsel = bn >> 6;
    size_t bcol_off = (size_t)hsel * EE * DK + (bn & 63);

    float2 pa[8];
    float  pb0[8], pb1[8];

    const int NB = EE / 32;   // 24

    // prologue: tile 0 -> regs -> stage0; tile 1 -> regs
    #pragma unroll
    for (int i = 0; i < 8; i++)
        pa[i] = *(const float2*)&A[(size_t)(m0 + ar + i*16) * EE + 2*ak2];
    #pragma unroll
    for (int i = 0; i < 8; i++) {
        pb0[i] = Bbase[(size_t)(2*(bk2 + i*2))     * DK + bcol_off];
        pb1[i] = Bbase[(size_t)(2*(bk2 + i*2) + 1) * DK + bcol_off];
    }
    #pragma unroll
    for (int i = 0; i < 8; i++)
        split2(pa[i].x, pa[i].y, dsm[(ar + i*16)*GW + ak2], dsm[2560 + (ar + i*16)*GW + ak2]);
    #pragma unroll
    for (int i = 0; i < 8; i++)
        split2(pb0[i], pb1[i], dsm[5120 + bn*GW + bk2 + i*2], dsm[7680 + bn*GW + bk2 + i*2]);
    {
        int kn = 32;
        #pragma unroll
        for (int i = 0; i < 8; i++)
            pa[i] = *(const float2*)&A[(size_t)(m0 + ar + i*16) * EE + kn + 2*ak2];
        #pragma unroll
        for (int i = 0; i < 8; i++) {
            pb0[i] = Bbase[(size_t)(kn + 2*(bk2 + i*2))     * DK + bcol_off];
            pb1[i] = Bbase[(size_t)(kn + 2*(bk2 + i*2) + 1) * DK + bcol_off];
        }
    }

    for (int ib = 0; ib < NB; ib++) {
        __syncthreads();
        int sb = (ib & 1) * GEMM_STAGE;
        int sn = ((ib + 1) & 1) * GEMM_STAGE;
        if (ib + 1 < NB) {
            #pragma unroll
            for (int i = 0; i < 8; i++)
                split2(pa[i].x, pa[i].y, dsm[sn + (ar + i*16)*GW + ak2],
                                         dsm[sn + 2560 + (ar + i*16)*GW + ak2]);
            #pragma unroll
            for (int i = 0; i < 8; i++)
                split2(pb0[i], pb1[i], dsm[sn + 5120 + bn*GW + bk2 + i*2],
                                       dsm[sn + 7680 + bn*GW + bk2 + i*2]);
        }
        if (ib + 2 < NB) {
            int kn = (ib + 2) * 32;
            #pragma unroll
            for (int i = 0; i < 8; i++)
                pa[i] = *(const float2*)&A[(size_t)(m0 + ar + i*16) * EE + kn + 2*ak2];
            #pragma unroll
            for (int i = 0; i < 8; i++) {
                pb0[i] = Bbase[(size_t)(kn + 2*(bk2 + i*2))     * DK + bcol_off];
                pb1[i] = Bbase[(size_t)(kn + 2*(bk2 + i*2) + 1) * DK + bcol_off];
            }
        }
        #pragma unroll
        for (int kc = 0; kc < 2; kc++) {
            unsigned ah[4], al[4];
            ldsm_x4(ah, &dsm[sb + arow*GW + kc*8 + acol_q]);
            ldsm_x4(al, &dsm[sb + 2560 + arow*GW + kc*8 + acol_q]);
            #pragma unroll
            for (int n0p = 0; n0p < 8; n0p++) {
                unsigned bh[4], bl[4];
                int br = sb + 5120 + (n0p*16 + brow_off)*GW + kc*8 + bcol_q;
                ldsm_x4(bh, &dsm[br]);
                ldsm_x4(bl, &dsm[br + 2560]);
                mma16(acc[2*n0p],   ah, bh);
                mma16(acc[2*n0p],   ah, bl);
                mma16(acc[2*n0p],   al, bh);
                mma16(acc[2*n0p+1], ah, bh+2);
                mma16(acc[2*n0p+1], ah, bl+2);
                mma16(acc[2*n0p+1], al, bh+2);
            }
        }
    }

    unsigned* Gh = (which == 0) ? g_Qh : (which == 1) ? g_Kh : g_Vh;
    unsigned* Gl = (which == 0) ? g_Ql : (which == 1) ? g_Kl : g_Vl;
    float sc = (which == 0) ? 0.125f : 1.0f;

    int rg1 = m0 + r0, rg2 = rg1 + 8;
    int b1 = rg1 >> 11, s1 = rg1 & 2047;
    int b2 = rg2 >> 11, s2 = rg2 & 2047;
    #pragma unroll
    for (int nb = 0; nb < 16; nb++) {
        int nloc = nb*8 + 2*t4;
        int head = (rem + nloc) >> 6;
        int wd = (nloc & 63) >> 1;
        size_t p1 = ((size_t)(b1*HH + head)*SS + s1) * 32 + wd;
        size_t p2 = ((size_t)(b2*HH + head)*SS + s2) * 32 + wd;
        unsigned hi, lo;
        split2(acc[nb][0]*sc, acc[nb][1]*sc, hi, lo);
        Gh[p1] = hi; Gl[p1] = lo;
        split2(acc[nb][2]*sc, acc[nb][3]*sc, hi, lo);
        Gh[p2] = hi; Gl[p2] = lo;
    }
}

// ---------------------------------------------------------------------------
// Flash attention, 3xBF16, register softmax, 2-stage smem pipeline with
// reg-bounced K/V copies. grid=(S/128, H, B), block=256.
// Stage layout (words): Kh 0 | Kl 2304 | Vh 4608 | Vl 6912 ; stage stride 9216.
// ---------------------------------------------------------------------------
#define KW 36
#define QR 128
#define FL_STAGE (4*64*KW)             // 9216 words
#define FLASH_SMEM (2*FL_STAGE*4)      // 73728 bytes

__global__ __launch_bounds__(256, 2) void flash_kernel(const int* __restrict__ mask)
{
    extern __shared__ unsigned SB[];

    int qt = blockIdx.x, h = blockIdx.y, b = blockIdx.z;
    int t = threadIdx.x, w = t >> 5, l = t & 31;
    int t4 = l & 3;
    int g = l >> 2;
    int lj = l >> 3, lr = l & 7;
    int r0 = 16*w + g;

    size_t qbase = ((size_t)(b*HH + h)*SS + qt*QR) * 32;
    size_t kvbase = (size_t)(b*HH + h) * SS * 32;
    const int* Mp = mask + ((size_t)b*SS + qt*QR) * SS;

    int arow = 16*w + lr + (lj & 1) * 8;
    int acol_q = (lj >> 1) * 4;
    int brow_off = lr + (lj >> 1) * 8;
    int bcol_q = (lj & 1) * 4;
    int vrow_off = (lj & 1) * 8 + lr;
    int vcol_q = (lj >> 1) * 4;

    // Stage Q words into stage0 area, pull fragments to regs.
    #pragma unroll
    for (int i = 0; i < 16; i++) {
        int idx = t + i * 256;
        int r = idx >> 5, k2 = idx & 31;
        SB[r*KW + k2]         = g_Qh[qbase + r*32 + k2];
        SB[QR*KW + r*KW + k2] = g_Ql[qbase + r*32 + k2];
    }
    __syncthreads();

    unsigned qfh[4][4], qfl[4][4];
    #pragma unroll
    for (int kc = 0; kc < 4; kc++) {
        ldsm_x4(qfh[kc], &SB[arow*KW + kc*8 + acol_q]);
        ldsm_x4(qfl[kc], &SB[QR*KW + arow*KW + kc*8 + acol_q]);
    }
    __syncthreads();   // done reading Q staging; stage0 free for tile 0

    // per-thread copy addressing: row = t>>2 (0..63), word col base = (t&3)*8
    int srow = t >> 2, scol = (t & 3) * 8;
    int srcoff = srow*32 + scol;            // in gmem tile
    int dstoff = srow*KW + scol;            // in smem section

    // prologue: tile 0 -> stage0 (direct)
    {
        size_t tb = kvbase + (size_t)0 + srcoff;
        uint4 a0 = *(const uint4*)&g_Kh[tb], a1 = *(const uint4*)&g_Kh[tb + 4];
        uint4 b0 = *(const uint4*)&g_Kl[tb], b1 = *(const uint4*)&g_Kl[tb + 4];
        uint4 c0 = *(const uint4*)&g_Vh[tb], c1 = *(const uint4*)&g_Vh[tb + 4];
        uint4 d0 = *(const uint4*)&g_Vl[tb], d1 = *(const uint4*)&g_Vl[tb + 4];
        *(uint4*)&SB[dstoff]          = a0; *(uint4*)&SB[dstoff + 4]          = a1;
        *(uint4*)&SB[2304 + dstoff]   = b0; *(uint4*)&SB[2304 + dstoff + 4]   = b1;
        *(uint4*)&SB[4608 + dstoff]   = c0; *(uint4*)&SB[4608 + dstoff + 4]   = c1;
        *(uint4*)&SB[6912 + dstoff]   = d0; *(uint4*)&SB[6912 + dstoff + 4]   = d1;
    }
    // preload K(1) into regs
    uint4 kr0, kr1, kr2, kr3;
    {
        size_t tb = kvbase + (size_t)(64*32) + srcoff;
        kr0 = *(const uint4*)&g_Kh[tb]; kr1 = *(const uint4*)&g_Kh[tb + 4];
        kr2 = *(const uint4*)&g_Kl[tb]; kr3 = *(const uint4*)&g_Kl[tb + 4];
    }

    float acc[8][4] = {};
    float m1 = -INFINITY, m2 = -INFINITY, l1 = 0.f, l2 = 0.f;

    const int NT = SS / 64;   // 32

    for (int kt = 0; kt < NT; kt++) {
        __syncthreads();
        int cs = (kt & 1) * FL_STAGE;
        int ns = ((kt + 1) & 1) * FL_STAGE;

        // ---- QK^T on current stage ----
        float sacc[8][4] = {};
        #pragma unroll
        for (int kc = 0; kc < 4; kc++) {
            #pragma unroll
            for (int n0p = 0; n0p < 4; n0p++) {
                unsigned bh[4], bl[4];
                int br = cs + (n0p*16 + brow_off)*KW + kc*8 + bcol_q;
                ldsm_x4(bh, &SB[br]);
                ldsm_x4(bl, &SB[br + 2304]);
                mma16(sacc[2*n0p],   qfh[kc], bh);
                mma16(sacc[2*n0p],   qfh[kc], bl);
                mma16(sacc[2*n0p],   qfl[kc], bh);
                mma16(sacc[2*n0p+1], qfh[kc], bh+2);
                mma16(sacc[2*n0p+1], qfh[kc], bl+2);
                mma16(sacc[2*n0p+1], qfl[kc], bh+2);
            }
        }

        // store K(kt+1) regs -> next stage; start V(kt+1) loads
        uint4 vr0, vr1, vr2, vr3;
        if (kt + 1 < NT) {
            *(uint4*)&SB[ns + dstoff]        = kr0;
            *(uint4*)&SB[ns + dstoff + 4]    = kr1;
            *(uint4*)&SB[ns + 2304 + dstoff]     = kr2;
            *(uint4*)&SB[ns + 2304 + dstoff + 4] = kr3;
            size_t tb = kvbase + (size_t)((kt+1)*64*32) + srcoff;
            vr0 = *(const uint4*)&g_Vh[tb]; vr1 = *(const uint4*)&g_Vh[tb + 4];
            vr2 = *(const uint4*)&g_Vl[tb]; vr3 = *(const uint4*)&g_Vl[tb + 4];
        }

        // ---- mask + online softmax, registers ----
        const int* Mr1 = Mp + (size_t)r0 * SS + kt*64;
        const int* Mr2 = Mp + (size_t)(r0 + 8) * SS + kt*64;
        #pragma unroll
        for (int n0 = 0; n0 < 8; n0++) {
            int2 ma = *(const int2*)&Mr1[n0*8 + 2*t4];
            int2 mb = *(const int2*)&Mr2[n0*8 + 2*t4];
            sacc[n0][0] = ma.x ? sacc[n0][0] : -1e9f;
            sacc[n0][1] = ma.y ? sacc[n0][1] : -1e9f;
            sacc[n0][2] = mb.x ? sacc[n0][2] : -1e9f;
            sacc[n0][3] = mb.y ? sacc[n0][3] : -1e9f;
        }
        float mx1 = -INFINITY, mx2 = -INFINITY;
        #pragma unroll
        for (int n0 = 0; n0 < 8; n0++) {
            mx1 = fmaxf(mx1, fmaxf(sacc[n0][0], sacc[n0][1]));
            mx2 = fmaxf(mx2, fmaxf(sacc[n0][2], sacc[n0][3]));
        }
        mx1 = fmaxf(mx1, __shfl_xor_sync(0xffffffffu, mx1, 1));
        mx1 = fmaxf(mx1, __shfl_xor_sync(0xffffffffu, mx1, 2));
        mx2 = fmaxf(mx2, __shfl_xor_sync(0xffffffffu, mx2, 1));
        mx2 = fmaxf(mx2, __shfl_xor_sync(0xffffffffu, mx2, 2));
        float mn1 = fmaxf(m1, mx1), mn2 = fmaxf(m2, mx2);
        float cr1 = __expf(m1 - mn1), cr2 = __expf(m2 - mn2);
        float ls1 = 0.f, ls2 = 0.f;
        #pragma unroll
        for (int n0 = 0; n0 < 8; n0++) {
            float p0 = __expf(sacc[n0][0] - mn1);
            float p1 = __expf(sacc[n0][1] - mn1);
            float p2 = __expf(sacc[n0][2] - mn2);
            float p3 = __expf(sacc[n0][3] - mn2);
            ls1 += p0 + p1; ls2 += p2 + p3;
            sacc[n0][0] = p0; sacc[n0][1] = p1;
            sacc[n0][2] = p2; sacc[n0][3] = p3;
        }
        ls1 += __shfl_xor_sync(0xffffffffu, ls1, 1);
        ls1 += __shfl_xor_sync(0xffffffffu, ls1, 2);
        ls2 += __shfl_xor_sync(0xffffffffu, ls2, 1);
        ls2 += __shfl_xor_sync(0xffffffffu, ls2, 2);
        m1 = mn1; m2 = mn2;
        l1 = l1 * cr1 + ls1;
        l2 = l2 * cr2 + ls2;

        // ---- PV on current stage ----
        #pragma unroll
        for (int n0 = 0; n0 < 8; n0++) {
            acc[n0][0] *= cr1; acc[n0][1] *= cr1;
            acc[n0][2] *= cr2; acc[n0][3] *= cr2;
        }
        #pragma unroll
        for (int kc = 0; kc < 4; kc++) {
            unsigned ah[4], al[4];
            split2(sacc[2*kc][0],   sacc[2*kc][1],   ah[0], al[0]);
            split2(sacc[2*kc][2],   sacc[2*kc][3],   ah[1], al[1]);
            split2(sacc[2*kc+1][0], sacc[2*kc+1][1], ah[2], al[2]);
            split2(sacc[2*kc+1][2], sacc[2*kc+1][3], ah[3], al[3]);
            #pragma unroll
            for (int n0p = 0; n0p < 4; n0p++) {
                unsigned bh[4], bl[4];
                int vbr = cs + 4608 + (kc*16 + vrow_off)*KW + n0p*8 + vcol_q;
                ldsm_x4_trans(bh, &SB[vbr]);
                ldsm_x4_trans(bl, &SB[vbr + 2304]);
                mma16(acc[2*n0p],   ah, bh);
                mma16(acc[2*n0p],   ah, bl);
                mma16(acc[2*n0p],   al, bh);
                mma16(acc[2*n0p+1], ah, bh+2);
                mma16(acc[2*n0p+1], ah, bl+2);
                mma16(acc[2*n0p+1], al, bh+2);
            }
        }

        // store V(kt+1) regs -> next stage; start K(kt+2) loads
        if (kt + 1 < NT) {
            *(uint4*)&SB[ns + 4608 + dstoff]         = vr0;
            *(uint4*)&SB[ns + 4608 + dstoff + 4]     = vr1;
            *(uint4*)&SB[ns + 6912 + dstoff]         = vr2;
            *(uint4*)&SB[ns + 6912 + dstoff + 4]     = vr3;
        }
        if (kt + 2 < NT) {
            size_t tb = kvbase + (size_t)((kt+2)*64*32) + srcoff;
            kr0 = *(const uint4*)&g_Kh[tb]; kr1 = *(const uint4*)&g_Kh[tb + 4];
            kr2 = *(const uint4*)&g_Kl[tb]; kr3 = *(const uint4*)&g_Kl[tb + 4];
        }
    }

    float inv1 = 1.f / l1;
    float inv2 = 1.f / l2;
    size_t row1 = (size_t)b*SS + qt*QR + r0;
    #pragma unroll
    for (int n0 = 0; n0 < 8; n0++) {
        int wd = h*32 + n0*4 + t4;
        unsigned hi, lo;
        split2(acc[n0][0]*inv1, acc[n0][1]*inv1, hi, lo);
        g_Ch[row1*384 + wd] = hi; g_Cl[row1*384 + wd] = lo;
        split2(acc[n0][2]*inv2, acc[n0][3]*inv2, hi, lo);
        g_Ch[(row1+8)*384 + wd] = hi; g_Cl[(row1+8)*384 + wd] = lo;
    }
}

// ---------------------------------------------------------------------------
// Output projection: packed C @ Wo -> f32 out. 128x128 tiles, 2-stage pipeline.
// grid=(32, 6).
// ---------------------------------------------------------------------------
__global__ __launch_bounds__(256) void out_gemm_kernel(
    const float* __restrict__ Wo, float* __restrict__ outp)
{
    extern __shared__ unsigned dsm[];

    int bx = blockIdx.x, by = blockIdx.y;
    int t = threadIdx.x, w = t >> 5, l = t & 31;
    int t4 = l & 3;
    int g = l >> 2;
    int lj = l >> 3, lr = l & 7;
    int m0 = bx * 128;
    int n0 = by * 128;

    const float* Bbase = Wo + n0;

    float acc[16][4] = {};
    int r0 = 16*w + g;

    int arow = 16*w + lr + (lj & 1) * 8;
    int acol_q = (lj >> 1) * 4;
    int brow_off = lr + (lj >> 1) * 8;
    int bcol_q = (lj & 1) * 4;

    int ar = t >> 4, ak2 = t & 15;
    int bn = t & 127, bk2 = t >> 7;

    unsigned pah[8], pal[8];
    float    pb0[8], pb1[8];

    const int NB = 384 / 16;   // 24

    // prologue
    #pragma unroll
    for (int i = 0; i < 8; i++) {
        size_t src = (size_t)(m0 + ar + i*16) * 384 + ak2;
        pah[i] = g_Ch[src];
        pal[i] = g_Cl[src];
    }
    #pragma unroll
    for (int i = 0; i < 8; i++) {
        pb0[i] = Bbase[(size_t)(2*(bk2 + i*2))     * EE + bn];
        pb1[i] = Bbase[(size_t)(2*(bk2 + i*2) + 1) * EE + bn];
    }
    #pragma unroll
    for (int i = 0; i < 8; i++) {
        dsm[(ar + i*16)*GW + ak2]        = pah[i];
        dsm[2560 + (ar + i*16)*GW + ak2] = pal[i];
    }
    #pragma unroll
    for (int i = 0; i < 8; i++)
        split2(pb0[i], pb1[i], dsm[5120 + bn*GW + bk2 + i*2], dsm[7680 + bn*GW + bk2 + i*2]);
    {
        int knw = 16;
        #pragma unroll
        for (int i = 0; i < 8; i++) {
            size_t src = (size_t)(m0 + ar + i*16) * 384 + knw + ak2;
            pah[i] = g_Ch[src];
            pal[i] = g_Cl[src];
        }
        #pragma unroll
        for (int i = 0; i < 8; i++) {
            pb0[i] = Bbase[(size_t)(2*(knw + bk2 + i*2))     * EE + bn];
            pb1[i] = Bbase[(size_t)(2*(knw + bk2 + i*2) + 1) * EE + bn];
        }
    }

    for (int ib = 0; ib < NB; ib++) {
        __syncthreads();
        int sb = (ib & 1) * GEMM_STAGE;
        int sn = ((ib + 1) & 1) * GEMM_STAGE;
        if (ib + 1 < NB) {
            #pragma unroll
            for (int i = 0; i < 8; i++) {
                dsm[sn + (ar + i*16)*GW + ak2]        = pah[i];
                dsm[sn + 2560 + (ar + i*16)*GW + ak2] = pal[i];
            }
            #pragma unroll
            for (int i = 0; i < 8; i++)
                split2(pb0[i], pb1[i], dsm[sn + 5120 + bn*GW + bk2 + i*2],
                                       dsm[sn + 7680 + bn*GW + bk2 + i*2]);
        }
        if (ib + 2 < NB) {
            int knw = (ib + 2) * 16;
            #pragma unroll
            for (int i = 0; i < 8; i++) {
                size_t src = (size_t)(m0 + ar + i*16) * 384 + knw + ak2;
                pah[i] = g_Ch[src];
                pal[i] = g_Cl[src];
            }
            #pragma unroll
            for (int i = 0; i < 8; i++) {
                pb0[i] = Bbase[(size_t)(2*(knw + bk2 + i*2))     * EE + bn];
                pb1[i] = Bbase[(size_t)(2*(knw + bk2 + i*2) + 1) * EE + bn];
            }
        }
        #pragma unroll
        for (int kc = 0; kc < 2; kc++) {
            unsigned ah[4], al[4];
            ldsm_x4(ah, &dsm[sb + arow*GW + kc*8 + acol_q]);
            ldsm_x4(al, &dsm[sb + 2560 + arow*GW + kc*8 + acol_q]);
            #pragma unroll
            for (int n0p = 0; n0p < 8; n0p++) {
                unsigned bh[4], bl[4];
                int br = sb + 5120 + (n0p*16 + brow_off)*GW + kc*8 + bcol_q;
                ldsm_x4(bh, &dsm[br]);
                ldsm_x4(bl, &dsm[br + 2560]);
                mma16(acc[2*n0p],   ah, bh);
                mma16(acc[2*n0p],   ah, bl);
                mma16(acc[2*n0p],   al, bh);
                mma16(acc[2*n0p+1], ah, bh+2);
                mma16(acc[2*n0p+1], ah, bl+2);
                mma16(acc[2*n0p+1], al, bh+2);
            }
        }
    }

    int rg1 = m0 + r0, rg2 = rg1 + 8;
    #pragma unroll
    for (int nb = 0; nb < 16; nb++) {
        int cn = n0 + nb*8 + 2*t4;
        *(float2*)&outp[(size_t)rg1 * EE + cn] = make_float2(acc[nb][0], acc[nb][1]);
        *(float2*)&outp[(size_t)rg2 * EE + cn] = make_float2(acc[nb][2], acc[nb][3]);
    }
}

// ---------------------------------------------------------------------------
extern "C" void kernel_launch(void* const* d_in, const int* in_sizes, int n_in,
                              void* d_out, int out_size)
{
    const float* q    = (const float*)d_in[0];
    const float* k    = (const float*)d_in[1];
    const float* v    = (const float*)d_in[2];
    const int*   mask = (const int*)  d_in[3];
    const float* Wq   = (const float*)d_in[4];
    const float* Wk   = (const float*)d_in[5];
    const float* Wv   = (const float*)d_in[6];
    const float* W    = (const float*)d_in[7];
    float* out = (float*)d_out;

    cudaFuncSetAttribute(qkv_gemm_kernel,
                         cudaFuncAttributeMaxDynamicSharedMemorySize, GEMM_SMEM);
    cudaFuncSetAttribute(flash_kernel,
                         cudaFuncAttributeMaxDynamicSharedMemorySize, FLASH_SMEM);
    cudaFuncSetAttribute(out_gemm_kernel,
                         cudaFuncAttributeMaxDynamicSharedMemorySize, GEMM_SMEM);

    qkv_gemm_kernel<<<dim3((BB*SS)/128, (3*EE)/128), 256, GEMM_SMEM>>>(q, k, v, Wq, Wk, Wv);
    flash_kernel<<<dim3(SS/QR, HH, BB), 256, FLASH_SMEM>>>(mask);
    out_gemm_kernel<<<dim3((BB*SS)/128, EE/128), 256, GEMM_SMEM>>>(W, out);
}

// round 16
// speedup vs baseline: 1.1221x; 1.1221x over previous
#include <cuda_runtime.h>
#include <cuda_bf16.h>
#include <math.h>

#define BB 2
#define SS 2048
#define EE 768
#define HH 12
#define DK 64

// Packed bf16x2 hi/lo interchange buffers (allocation-free)
__device__ unsigned g_Qh[BB*HH*SS*32], g_Ql[BB*HH*SS*32];  // [bhs][dk2], pre-scaled 1/8
__device__ unsigned g_Kh[BB*HH*SS*32], g_Kl[BB*HH*SS*32];  // [bhs][dk2]
__device__ unsigned g_Vh[BB*HH*SS*32], g_Vl[BB*HH*SS*32];  // [bhs][dk2]
__device__ unsigned g_Ch[BB*SS*384],  g_Cl[BB*SS*384];     // concat [m][e2]

__device__ __forceinline__ void split2(float x0, float x1, unsigned& hi, unsigned& lo) {
    __nv_bfloat162 h2 = __floats2bfloat162_rn(x0, x1);
    float h0 = __bfloat162float(__low2bfloat16(h2));
    float h1 = __bfloat162float(__high2bfloat16(h2));
    __nv_bfloat162 l2 = __floats2bfloat162_rn(x0 - h0, x1 - h1);
    hi = *reinterpret_cast<unsigned*>(&h2);
    lo = *reinterpret_cast<unsigned*>(&l2);
}

__device__ __forceinline__ void mma16(float c[4], const unsigned a[4], const unsigned* b) {
    asm volatile(
        "mma.sync.aligned.m16n8k16.row.col.f32.bf16.bf16.f32 "
        "{%0,%1,%2,%3},{%4,%5,%6,%7},{%8,%9},{%0,%1,%2,%3};"
        : "+f"(c[0]), "+f"(c[1]), "+f"(c[2]), "+f"(c[3])
        : "r"(a[0]), "r"(a[1]), "r"(a[2]), "r"(a[3]), "r"(b[0]), "r"(b[1]));
}

__device__ __forceinline__ void ldsm_x4(unsigned r[4], const void* p) {
    unsigned addr = (unsigned)__cvta_generic_to_shared(p);
    asm volatile("ldmatrix.sync.aligned.m8n8.x4.shared.b16 {%0,%1,%2,%3}, [%4];"
                 : "=r"(r[0]), "=r"(r[1]), "=r"(r[2]), "=r"(r[3]) : "r"(addr));
}

__device__ __forceinline__ void ldsm_x4_trans(unsigned r[4], const void* p) {
    unsigned addr = (unsigned)__cvta_generic_to_shared(p);
    asm volatile("ldmatrix.sync.aligned.m8n8.x4.trans.shared.b16 {%0,%1,%2,%3}, [%4];"
                 : "=r"(r[0]), "=r"(r[1]), "=r"(r[2]), "=r"(r[3]) : "r"(addr));
}

__device__ __forceinline__ void cpa16(unsigned* smem_dst, const unsigned* gsrc) {
    unsigned daddr = (unsigned)__cvta_generic_to_shared(smem_dst);
    asm volatile("cp.async.cg.shared.global [%0], [%1], 16;" :: "r"(daddr), "l"(gsrc));
}

#define GW 20

// ---------------------------------------------------------------------------
// Fused QKV GEMM: X[4096,768] @ Wall[768,2304], 128x128 tiles, 256 threads,
// register-prefetch pipelined. grid=(32,18). Epilogue writes PACKED hi/lo
// bf16x2 Q (x 1/8), K, V.   (R13-proven version)
// ---------------------------------------------------------------------------
__global__ __launch_bounds__(256) void qkv_gemm_kernel(
    const float* __restrict__ Xq, const float* __restrict__ Xk, const float* __restrict__ Xv,
    const float* __restrict__ Wq, const float* __restrict__ Wk, const float* __restrict__ Wv)
{
    __shared__ unsigned Ah[128*GW], Al[128*GW];   // [row][k2]
    __shared__ unsigned Bh[128*GW], Bl[128*GW];   // [n][k2]

    int bx = blockIdx.x, by = blockIdx.y;
    int t = threadIdx.x, w = t >> 5, l = t & 31;
    int t4 = l & 3;
    int g = l >> 2;
    int lj = l >> 3, lr = l & 7;
    int m0 = bx * 128;
    int n0 = by * 128;

    int which = n0 / EE;
    int rem = n0 - which * EE;               // multiple of 128
    const float* A  = (which == 0) ? Xq : (which == 1) ? Xk : Xv;
    const float* Ws = (which == 0) ? Wq : (which == 1) ? Wk : Wv;
    const float* Bbase = Ws + (size_t)(rem / 64) * EE * DK;

    float acc[16][4] = {};
    int r0 = 16*w + g;

    int arow = 16*w + lr + (lj & 1) * 8;
    int acol_q = (lj >> 1) * 4;
    int brow_off = lr + (lj >> 1) * 8;
    int bcol_q = (lj & 1) * 4;

    int ar = t >> 4, ak2 = t & 15;
    int bn = t & 127, bk2 = t >> 7;
    int hsel = bn >> 6;
    size_t bcol_off = (size_t)hsel * EE * DK + (bn & 63);

    float2 pa[8];
    float  pb0[8], pb1[8];

    #pragma unroll
    for (int i = 0; i < 8; i++)
        pa[i] = *(const float2*)&A[(size_t)(m0 + ar + i*16) * EE + 2*ak2];
    #pragma unroll
    for (int i = 0; i < 8; i++) {
        pb0[i] = Bbase[(size_t)(2*(bk2 + i*2))     * DK + bcol_off];
        pb1[i] = Bbase[(size_t)(2*(bk2 + i*2) + 1) * DK + bcol_off];
    }

    for (int k0 = 0; k0 < EE; k0 += 32) {
        __syncthreads();
        #pragma unroll
        for (int i = 0; i < 8; i++)
            split2(pa[i].x, pa[i].y, Ah[(ar + i*16)*GW + ak2], Al[(ar + i*16)*GW + ak2]);
        #pragma unroll
        for (int i = 0; i < 8; i++)
            split2(pb0[i], pb1[i], Bh[bn*GW + bk2 + i*2], Bl[bn*GW + bk2 + i*2]);
        __syncthreads();

        if (k0 + 32 < EE) {
            int kn = k0 + 32;
            #pragma unroll
            for (int i = 0; i < 8; i++)
                pa[i] = *(const float2*)&A[(size_t)(m0 + ar + i*16) * EE + kn + 2*ak2];
            #pragma unroll
            for (int i = 0; i < 8; i++) {
                pb0[i] = Bbase[(size_t)(kn + 2*(bk2 + i*2))     * DK + bcol_off];
                pb1[i] = Bbase[(size_t)(kn + 2*(bk2 + i*2) + 1) * DK + bcol_off];
            }
        }

        #pragma unroll
        for (int kc = 0; kc < 2; kc++) {
            unsigned ah[4], al[4];
            ldsm_x4(ah, &Ah[arow*GW + kc*8 + acol_q]);
            ldsm_x4(al, &Al[arow*GW + kc*8 + acol_q]);
            #pragma unroll
            for (int n0p = 0; n0p < 8; n0p++) {
                unsigned bh[4], bl[4];
                int br = (n0p*16 + brow_off)*GW + kc*8 + bcol_q;
                ldsm_x4(bh, &Bh[br]);
                ldsm_x4(bl, &Bl[br]);
                mma16(acc[2*n0p],   ah, bh);
                mma16(acc[2*n0p],   ah, bl);
                mma16(acc[2*n0p],   al, bh);
                mma16(acc[2*n0p+1], ah, bh+2);
                mma16(acc[2*n0p+1], ah, bl+2);
                mma16(acc[2*n0p+1], al, bh+2);
            }
        }
    }

    unsigned* Gh = (which == 0) ? g_Qh : (which == 1) ? g_Kh : g_Vh;
    unsigned* Gl = (which == 0) ? g_Ql : (which == 1) ? g_Kl : g_Vl;
    float sc = (which == 0) ? 0.125f : 1.0f;

    int rg1 = m0 + r0, rg2 = rg1 + 8;
    int b1 = rg1 >> 11, s1 = rg1 & 2047;
    int b2 = rg2 >> 11, s2 = rg2 & 2047;
    #pragma unroll
    for (int nb = 0; nb < 16; nb++) {
        int nloc = nb*8 + 2*t4;
        int head = (rem + nloc) >> 6;
        int wd = (nloc & 63) >> 1;
        size_t p1 = ((size_t)(b1*HH + head)*SS + s1) * 32 + wd;
        size_t p2 = ((size_t)(b2*HH + head)*SS + s2) * 32 + wd;
        unsigned hi, lo;
        split2(acc[nb][0]*sc, acc[nb][1]*sc, hi, lo);
        Gh[p1] = hi; Gl[p1] = lo;
        split2(acc[nb][2]*sc, acc[nb][3]*sc, hi, lo);
        Gh[p2] = hi; Gl[p2] = lo;
    }
}

// ---------------------------------------------------------------------------
// Flash attention, 3xBF16, register softmax, cp.async 2-stage pipeline.
// grid=(S/128, H, B), block=256. Stage layout (words):
//   Kh 0 | Kl 2304 | Vh 4608 | Vl 6912 ; stage stride 9216.
// cp.async keeps prefetch out of the register file (the R14 failure mode).
// ---------------------------------------------------------------------------
#define KW 36
#define QR 128
#define FL_STAGE (4*64*KW)             // 9216 words
#define FLASH_SMEM (2*FL_STAGE*4)      // 73728 bytes

__global__ __launch_bounds__(256, 2) void flash_kernel(const int* __restrict__ mask)
{
    extern __shared__ unsigned SB[];

    int qt = blockIdx.x, h = blockIdx.y, b = blockIdx.z;
    int t = threadIdx.x, w = t >> 5, l = t & 31;
    int t4 = l & 3;
    int g = l >> 2;
    int lj = l >> 3, lr = l & 7;
    int r0 = 16*w + g;

    size_t qbase = ((size_t)(b*HH + h)*SS + qt*QR) * 32;
    size_t kvbase = (size_t)(b*HH + h) * SS * 32;
    const int* Mp = mask + ((size_t)b*SS + qt*QR) * SS;

    int arow = 16*w + lr + (lj & 1) * 8;
    int acol_q = (lj >> 1) * 4;
    int brow_off = lr + (lj >> 1) * 8;       // K (non-trans)
    int bcol_q = (lj & 1) * 4;
    int vrow_off = (lj & 1) * 8 + lr;        // V (trans)
    int vcol_q = (lj >> 1) * 4;

    // Stage Q words into stage0 area, pull fragments to regs.
    #pragma unroll
    for (int i = 0; i < 16; i++) {
        int idx = t + i * 256;
        int r = idx >> 5, k2 = idx & 31;
        SB[r*KW + k2]         = g_Qh[qbase + r*32 + k2];
        SB[QR*KW + r*KW + k2] = g_Ql[qbase + r*32 + k2];
    }
    __syncthreads();

    unsigned qfh[4][4], qfl[4][4];
    #pragma unroll
    for (int kc = 0; kc < 4; kc++) {
        ldsm_x4(qfh[kc], &SB[arow*KW + kc*8 + acol_q]);
        ldsm_x4(qfl[kc], &SB[QR*KW + arow*KW + kc*8 + acol_q]);
    }
    __syncthreads();   // all Q reads done; stage0 free for tile 0

    // copy addressing: row = t>>2 (0..63), word col base = (t&3)*8
    int srow = t >> 2, scol = (t & 3) * 8;
    int srcoff = srow*32 + scol;
    int dstoff = srow*KW + scol;

    const int NT = SS / 64;   // 32

    // issue one tile's K/V hi/lo into stage s (8 x 16B cp.async + commit)
    #define ISSUE_TILE(ktv, s) do {                                          \
        size_t tb = kvbase + (size_t)((ktv)*64*32) + srcoff;                 \
        cpa16(&SB[(s) + dstoff],            &g_Kh[tb]);                      \
        cpa16(&SB[(s) + dstoff + 4],        &g_Kh[tb + 4]);                  \
        cpa16(&SB[(s) + 2304 + dstoff],     &g_Kl[tb]);                      \
        cpa16(&SB[(s) + 2304 + dstoff + 4], &g_Kl[tb + 4]);                  \
        cpa16(&SB[(s) + 4608 + dstoff],     &g_Vh[tb]);                      \
        cpa16(&SB[(s) + 4608 + dstoff + 4], &g_Vh[tb + 4]);                  \
        cpa16(&SB[(s) + 6912 + dstoff],     &g_Vl[tb]);                      \
        cpa16(&SB[(s) + 6912 + dstoff + 4], &g_Vl[tb + 4]);                  \
        asm volatile("cp.async.commit_group;");                              \
    } while (0)

    ISSUE_TILE(0, 0);
    ISSUE_TILE(1, FL_STAGE);

    float acc[8][4] = {};
    float m1 = -INFINITY, m2 = -INFINITY, l1 = 0.f, l2 = 0.f;

    for (int kt = 0; kt < NT; kt++) {
        if (kt + 1 < NT) asm volatile("cp.async.wait_group 1;");
        else             asm volatile("cp.async.wait_group 0;");
        __syncthreads();
        int cs = (kt & 1) * FL_STAGE;

        // ---- QK^T on current stage ----
        float sacc[8][4] = {};
        #pragma unroll
        for (int kc = 0; kc < 4; kc++) {
            #pragma unroll
            for (int n0p = 0; n0p < 4; n0p++) {
                unsigned bh[4], bl[4];
                int br = cs + (n0p*16 + brow_off)*KW + kc*8 + bcol_q;
                ldsm_x4(bh, &SB[br]);
                ldsm_x4(bl, &SB[br + 2304]);
                mma16(sacc[2*n0p],   qfh[kc], bh);
                mma16(sacc[2*n0p],   qfh[kc], bl);
                mma16(sacc[2*n0p],   qfl[kc], bh);
                mma16(sacc[2*n0p+1], qfh[kc], bh+2);
                mma16(sacc[2*n0p+1], qfh[kc], bl+2);
                mma16(sacc[2*n0p+1], qfl[kc], bh+2);
            }
        }

        // ---- mask + online softmax, registers ----
        const int* Mr1 = Mp + (size_t)r0 * SS + kt*64;
        const int* Mr2 = Mp + (size_t)(r0 + 8) * SS + kt*64;
        #pragma unroll
        for (int n0 = 0; n0 < 8; n0++) {
            int2 ma = *(const int2*)&Mr1[n0*8 + 2*t4];
            int2 mb = *(const int2*)&Mr2[n0*8 + 2*t4];
            sacc[n0][0] = ma.x ? sacc[n0][0] : -1e9f;
            sacc[n0][1] = ma.y ? sacc[n0][1] : -1e9f;
            sacc[n0][2] = mb.x ? sacc[n0][2] : -1e9f;
            sacc[n0][3] = mb.y ? sacc[n0][3] : -1e9f;
        }
        float mx1 = -INFINITY, mx2 = -INFINITY;
        #pragma unroll
        for (int n0 = 0; n0 < 8; n0++) {
            mx1 = fmaxf(mx1, fmaxf(sacc[n0][0], sacc[n0][1]));
            mx2 = fmaxf(mx2, fmaxf(sacc[n0][2], sacc[n0][3]));
        }
        mx1 = fmaxf(mx1, __shfl_xor_sync(0xffffffffu, mx1, 1));
        mx1 = fmaxf(mx1, __shfl_xor_sync(0xffffffffu, mx1, 2));
        mx2 = fmaxf(mx2, __shfl_xor_sync(0xffffffffu, mx2, 1));
        mx2 = fmaxf(mx2, __shfl_xor_sync(0xffffffffu, mx2, 2));
        float mn1 = fmaxf(m1, mx1), mn2 = fmaxf(m2, mx2);
        float cr1 = __expf(m1 - mn1), cr2 = __expf(m2 - mn2);
        float ls1 = 0.f, ls2 = 0.f;
        #pragma unroll
        for (int n0 = 0; n0 < 8; n0++) {
            float p0 = __expf(sacc[n0][0] - mn1);
            float p1 = __expf(sacc[n0][1] - mn1);
            float p2 = __expf(sacc[n0][2] - mn2);
            float p3 = __expf(sacc[n0][3] - mn2);
            ls1 += p0 + p1; ls2 += p2 + p3;
            sacc[n0][0] = p0; sacc[n0][1] = p1;
            sacc[n0][2] = p2; sacc[n0][3] = p3;
        }
        ls1 += __shfl_xor_sync(0xffffffffu, ls1, 1);
        ls1 += __shfl_xor_sync(0xffffffffu, ls1, 2);
        ls2 += __shfl_xor_sync(0xffffffffu, ls2, 1);
        ls2 += __shfl_xor_sync(0xffffffffu, ls2, 2);
        m1 = mn1; m2 = mn2;
        l1 = l1 * cr1 + ls1;
        l2 = l2 * cr2 + ls2;

        // ---- PV on current stage ----
        #pragma unroll
        for (int n0 = 0; n0 < 8; n0++) {
            acc[n0][0] *= cr1; acc[n0][1] *= cr1;
            acc[n0][2] *= cr2; acc[n0][3] *= cr2;
        }
        #pragma unroll
        for (int kc = 0; kc < 4; kc++) {
            unsigned ah[4], al[4];
            split2(sacc[2*kc][0],   sacc[2*kc][1],   ah[0], al[0]);
            split2(sacc[2*kc][2],   sacc[2*kc][3],   ah[1], al[1]);
            split2(sacc[2*kc+1][0], sacc[2*kc+1][1], ah[2], al[2]);
            split2(sacc[2*kc+1][2], sacc[2*kc+1][3], ah[3], al[3]);
            #pragma unroll
            for (int n0p = 0; n0p < 4; n0p++) {
                unsigned bh[4], bl[4];
                int vbr = cs + 4608 + (kc*16 + vrow_off)*KW + n0p*8 + vcol_q;
                ldsm_x4_trans(bh, &SB[vbr]);
                ldsm_x4_trans(bl, &SB[vbr + 2304]);
                mma16(acc[2*n0p],   ah, bh);
                mma16(acc[2*n0p],   ah, bl);
                mma16(acc[2*n0p],   al, bh);
                mma16(acc[2*n0p+1], ah, bh+2);
                mma16(acc[2*n0p+1], ah, bl+2);
                mma16(acc[2*n0p+1], al, bh+2);
            }
        }

        __syncthreads();   // done reading stage cs; safe to refill it
        if (kt + 2 < NT) ISSUE_TILE(kt + 2, cs);
    }

    float inv1 = 1.f / l1;
    float inv2 = 1.f / l2;
    size_t row1 = (size_t)b*SS + qt*QR + r0;
    #pragma unroll
    for (int n0 = 0; n0 < 8; n0++) {
        int wd = h*32 + n0*4 + t4;
        unsigned hi, lo;
        split2(acc[n0][0]*inv1, acc[n0][1]*inv1, hi, lo);
        g_Ch[row1*384 + wd] = hi; g_Cl[row1*384 + wd] = lo;
        split2(acc[n0][2]*inv2, acc[n0][3]*inv2, hi, lo);
        g_Ch[(row1+8)*384 + wd] = hi; g_Cl[(row1+8)*384 + wd] = lo;
    }
}

// ---------------------------------------------------------------------------
// Output projection: packed C [4096, 384 words] @ Wo[768,768] -> f32 out.
// 128x128 tiles, 256 threads, pipelined. grid=(32, 6).  (R13-proven version)
// ---------------------------------------------------------------------------
__global__ __launch_bounds__(256) void out_gemm_kernel(
    const float* __restrict__ Wo, float* __restrict__ outp)
{
    __shared__ unsigned Ah[128*GW], Al[128*GW];
    __shared__ unsigned Bh[128*GW], Bl[128*GW];

    int bx = blockIdx.x, by = blockIdx.y;
    int t = threadIdx.x, w = t >> 5, l = t & 31;
    int t4 = l & 3;
    int g = l >> 2;
    int lj = l >> 3, lr = l & 7;
    int m0 = bx * 128;
    int n0 = by * 128;

    const float* Bbase = Wo + n0;

    float acc[16][4] = {};
    int r0 = 16*w + g;

    int arow = 16*w + lr + (lj & 1) * 8;
    int acol_q = (lj >> 1) * 4;
    int brow_off = lr + (lj >> 1) * 8;
    int bcol_q = (lj & 1) * 4;

    int ar = t >> 4, ak2 = t & 15;
    int bn = t & 127, bk2 = t >> 7;

    unsigned pah[8], pal[8];
    float    pb0[8], pb1[8];

    #pragma unroll
    for (int i = 0; i < 8; i++) {
        size_t src = (size_t)(m0 + ar + i*16) * 384 + ak2;
        pah[i] = g_Ch[src];
        pal[i] = g_Cl[src];
    }
    #pragma unroll
    for (int i = 0; i < 8; i++) {
        pb0[i] = Bbase[(size_t)(2*(bk2 + i*2))     * EE + bn];
        pb1[i] = Bbase[(size_t)(2*(bk2 + i*2) + 1) * EE + bn];
    }

    for (int kw = 0; kw < 384; kw += 16) {
        __syncthreads();
        #pragma unroll
        for (int i = 0; i < 8; i++) {
            Ah[(ar + i*16)*GW + ak2] = pah[i];
            Al[(ar + i*16)*GW + ak2] = pal[i];
        }
        #pragma unroll
        for (int i = 0; i < 8; i++)
            split2(pb0[i], pb1[i], Bh[bn*GW + bk2 + i*2], Bl[bn*GW + bk2 + i*2]);
        __syncthreads();

        if (kw + 16 < 384) {
            int knw = kw + 16;
            #pragma unroll
            for (int i = 0; i < 8; i++) {
                size_t src = (size_t)(m0 + ar + i*16) * 384 + knw + ak2;
                pah[i] = g_Ch[src];
                pal[i] = g_Cl[src];
            }
            #pragma unroll
            for (int i = 0; i < 8; i++) {
                pb0[i] = Bbase[(size_t)(2*(knw + bk2 + i*2))     * EE + bn];
                pb1[i] = Bbase[(size_t)(2*(knw + bk2 + i*2) + 1) * EE + bn];
            }
        }

        #pragma unroll
        for (int kc = 0; kc < 2; kc++) {
            unsigned ah[4], al[4];
            ldsm_x4(ah, &Ah[arow*GW + kc*8 + acol_q]);
            ldsm_x4(al, &Al[arow*GW + kc*8 + acol_q]);
            #pragma unroll
            for (int n0p = 0; n0p < 8; n0p++) {
                unsigned bh[4], bl[4];
                int br = (n0p*16 + brow_off)*GW + kc*8 + bcol_q;
                ldsm_x4(bh, &Bh[br]);
                ldsm_x4(bl, &Bl[br]);
                mma16(acc[2*n0p],   ah, bh);
                mma16(acc[2*n0p],   ah, bl);
                mma16(acc[2*n0p],   al, bh);
                mma16(acc[2*n0p+1], ah, bh+2);
                mma16(acc[2*n0p+1], ah, bl+2);
                mma16(acc[2*n0p+1], al, bh+2);
            }
        }
    }

    int rg1 = m0 + r0, rg2 = rg1 + 8;
    #pragma unroll
    for (int nb = 0; nb < 16; nb++) {
        int cn = n0 + nb*8 + 2*t4;
        *(float2*)&outp[(size_t)rg1 * EE + cn] = make_float2(acc[nb][0], acc[nb][1]);
        *(float2*)&outp[(size_t)rg2 * EE + cn] = make_float2(acc[nb][2], acc[nb][3]);
    }
}

// ---------------------------------------------------------------------------
extern "C" void kernel_launch(void* const* d_in, const int* in_sizes, int n_in,
                              void* d_out, int out_size)
{
    const float* q    = (const float*)d_in[0];
    const float* k    = (const float*)d_in[1];
    const float* v    = (const float*)d_in[2];
    const int*   mask = (const int*)  d_in[3];
    const float* Wq   = (const float*)d_in[4];
    const float* Wk   = (const float*)d_in[5];
    const float* Wv   = (const float*)d_in[6];
    const float* W    = (const float*)d_in[7];
    float* out = (float*)d_out;

    cudaFuncSetAttribute(flash_kernel,
                         cudaFuncAttributeMaxDynamicSharedMemorySize, FLASH_SMEM);

    qkv_gemm_kernel<<<dim3((BB*SS)/128, (3*EE)/128), 256>>>(q, k, v, Wq, Wk, Wv);
    flash_kernel<<<dim3(SS/QR, HH, BB), 256, FLASH_SMEM>>>(mask);
    out_gemm_kernel<<<dim3((BB*SS)/128, EE/128), 256>>>(W, out);
}